// round 5
// baseline (speedup 1.0000x reference)
#include <cuda_runtime.h>

// Problem constants
#define B_   2
#define S_   2048
#define D_   1024
#define H_   16
#define DK_  64
#define BH_  (B_*H_)          // 32
#define M_   (B_*S_)          // 4096 rows for projections

// ---------------- scratch (device globals; no allocations allowed) -------
__device__ float g_qh[BH_ * S_ * DK_];        // [B*H, S, DK] head-major
__device__ float g_kh[BH_ * S_ * DK_];
__device__ float g_vh[BH_ * S_ * DK_];
__device__ float g_scores[(size_t)BH_ * S_ * S_];  // 512 MB
__device__ float g_attn[M_ * D_];             // [B,S,D] attention output

// ---------------- shared-memory tile for 128x128x8 SGEMM ----------------
struct __align__(16) Tile {
    float As[8][128];   // As[k][m]
    float Bs[8][128];   // Bs[k][n]
};

// C tile accumulation: C[m0..m0+128)[n0..n0+128) += A[M,1024] @ W[1024,N]
// A row-major with row stride 1024, W row-major [1024, N] with row stride 1024.
// 256 threads, each computes 8x8 (rows {ty*4..+3, 64+ty*4..+3}, cols likewise with tx).
__device__ __forceinline__ void gemm128x128_k1024(
    const float* __restrict__ A, const float* __restrict__ W,
    int m0, int n0, Tile* t, float acc[8][8])
{
    const int tid  = threadIdx.x;
    const int tx   = tid & 15, ty = tid >> 4;
    const int arow = tid >> 1, aq = (tid & 1) * 4;   // A tile: 128 rows x 8 k
    const int brow = tid >> 5, bq = (tid & 31) * 4;  // B tile: 8 k x 128 n

    const float* Aptr = A + (size_t)(m0 + arow) * 1024 + aq;
    const float* Wptr = W + (size_t)brow * 1024 + n0 + bq;

    for (int k0 = 0; k0 < 1024; k0 += 8) {
        float4 av = *(const float4*)(Aptr + k0);
        float4 bv = *(const float4*)(Wptr + (size_t)k0 * 1024);
        __syncthreads();                      // prior iter reads done
        t->As[aq + 0][arow] = av.x;
        t->As[aq + 1][arow] = av.y;
        t->As[aq + 2][arow] = av.z;
        t->As[aq + 3][arow] = av.w;
        *(float4*)&t->Bs[brow][bq] = bv;
        __syncthreads();
#pragma unroll
        for (int kk = 0; kk < 8; kk++) {
            float a[8], b[8];
            *(float4*)&a[0] = *(const float4*)&t->As[kk][ty * 4];
            *(float4*)&a[4] = *(const float4*)&t->As[kk][64 + ty * 4];
            *(float4*)&b[0] = *(const float4*)&t->Bs[kk][tx * 4];
            *(float4*)&b[4] = *(const float4*)&t->Bs[kk][64 + tx * 4];
#pragma unroll
            for (int i = 0; i < 8; i++)
#pragma unroll
                for (int j = 0; j < 8; j++)
                    acc[i][j] = fmaf(a[i], b[j], acc[i][j]);
        }
    }
}

// ---------------- projection: C = X@W + b, scattered to head-major -------
template<int DST>
__global__ void __launch_bounds__(256, 2) proj_kernel(
    const float* __restrict__ X, const float* __restrict__ W,
    const float* __restrict__ bias)
{
    __shared__ Tile t;
    float acc[8][8] = {};
    const int m0 = blockIdx.y * 128, n0 = blockIdx.x * 128;
    gemm128x128_k1024(X, W, m0, n0, &t, acc);

    float* dst = (DST == 0) ? g_qh : (DST == 1) ? g_kh : g_vh;
    const int tx = threadIdx.x & 15, ty = threadIdx.x >> 4;
#pragma unroll
    for (int i = 0; i < 8; i++) {
        const int r = (i < 4) ? (ty * 4 + i) : (60 + ty * 4 + i);
        const int m = m0 + r;
        const int b = m >> 11;          // / S_
        const int s = m & 2047;
#pragma unroll
        for (int jg = 0; jg < 2; jg++) {
            const int n = n0 + jg * 64 + tx * 4;
            const int h = n >> 6;       // / DK_
            const int d = tx * 4;       // n & 63
            float4 bb = *(const float4*)&bias[n];
            float4 v;
            v.x = acc[i][jg * 4 + 0] + bb.x;
            v.y = acc[i][jg * 4 + 1] + bb.y;
            v.z = acc[i][jg * 4 + 2] + bb.z;
            v.w = acc[i][jg * 4 + 3] + bb.w;
            *(float4*)&dst[((size_t)(b * H_ + h) * S_ + s) * DK_ + d] = v;
        }
    }
}

// ---------------- scores: P[bh,i,j] = (Q.Kt)/8, masked ------------------
__global__ void __launch_bounds__(256, 2) scores_kernel(const int* __restrict__ mask)
{
    __shared__ Tile t;
    __shared__ int smask[128];
    const int tid = threadIdx.x;
    const int tx = tid & 15, ty = tid >> 4;
    const int bh = blockIdx.z;
    const int i0 = blockIdx.y * 128, j0 = blockIdx.x * 128;
    const int b  = bh >> 4;                    // / H_

    const float* Q = g_qh + (size_t)bh * S_ * DK_;
    const float* K = g_kh + (size_t)bh * S_ * DK_;

    if (tid < 128) smask[tid] = mask[b * S_ + j0 + tid];

    float acc[8][8] = {};
    const int lrow = tid >> 1, lq = (tid & 1) * 4;
    for (int k0 = 0; k0 < DK_; k0 += 8) {
        float4 av = *(const float4*)&Q[(size_t)(i0 + lrow) * DK_ + k0 + lq];
        float4 bv = *(const float4*)&K[(size_t)(j0 + lrow) * DK_ + k0 + lq];
        __syncthreads();
        t.As[lq + 0][lrow] = av.x; t.As[lq + 1][lrow] = av.y;
        t.As[lq + 2][lrow] = av.z; t.As[lq + 3][lrow] = av.w;
        t.Bs[lq + 0][lrow] = bv.x; t.Bs[lq + 1][lrow] = bv.y;
        t.Bs[lq + 2][lrow] = bv.z; t.Bs[lq + 3][lrow] = bv.w;
        __syncthreads();
#pragma unroll
        for (int kk = 0; kk < 8; kk++) {
            float a[8], bfr[8];
            *(float4*)&a[0]   = *(const float4*)&t.As[kk][ty * 4];
            *(float4*)&a[4]   = *(const float4*)&t.As[kk][64 + ty * 4];
            *(float4*)&bfr[0] = *(const float4*)&t.Bs[kk][tx * 4];
            *(float4*)&bfr[4] = *(const float4*)&t.Bs[kk][64 + tx * 4];
#pragma unroll
            for (int i = 0; i < 8; i++)
#pragma unroll
                for (int j = 0; j < 8; j++)
                    acc[i][j] = fmaf(a[i], bfr[j], acc[i][j]);
        }
    }

    float* P = g_scores + (size_t)bh * S_ * S_;
#pragma unroll
    for (int i = 0; i < 8; i++) {
        const int r = (i < 4) ? (ty * 4 + i) : (60 + ty * 4 + i);
        const size_t rowoff = (size_t)(i0 + r) * S_;
#pragma unroll
        for (int jg = 0; jg < 2; jg++) {
            const int c = jg * 64 + tx * 4;
            float4 v;
            // NOTE reference semantics: positions where mask != 0 get -1e10
            v.x = smask[c + 0] ? -1e10f : acc[i][jg * 4 + 0] * 0.125f;
            v.y = smask[c + 1] ? -1e10f : acc[i][jg * 4 + 1] * 0.125f;
            v.z = smask[c + 2] ? -1e10f : acc[i][jg * 4 + 2] * 0.125f;
            v.w = smask[c + 3] ? -1e10f : acc[i][jg * 4 + 3] * 0.125f;
            *(float4*)&P[rowoff + j0 + c] = v;
        }
    }
}

// ---------------- row softmax over 2048 keys, in place ------------------
__global__ void __launch_bounds__(256) softmax_kernel()
{
    const int tid = threadIdx.x;
    float* p = g_scores + (size_t)blockIdx.x * S_;

    float v[8];
#pragma unroll
    for (int k = 0; k < 8; k++) v[k] = p[tid + 256 * k];

    float m = v[0];
#pragma unroll
    for (int k = 1; k < 8; k++) m = fmaxf(m, v[k]);
#pragma unroll
    for (int o = 16; o; o >>= 1) m = fmaxf(m, __shfl_xor_sync(0xffffffffu, m, o));

    __shared__ float red[8];
    if ((tid & 31) == 0) red[tid >> 5] = m;
    __syncthreads();
    float bm = red[0];
#pragma unroll
    for (int w = 1; w < 8; w++) bm = fmaxf(bm, red[w]);

    float s = 0.f;
#pragma unroll
    for (int k = 0; k < 8; k++) { v[k] = __expf(v[k] - bm); s += v[k]; }
#pragma unroll
    for (int o = 16; o; o >>= 1) s += __shfl_xor_sync(0xffffffffu, s, o);
    __syncthreads();                 // everyone done reading red (max)
    if ((tid & 31) == 0) red[tid >> 5] = s;
    __syncthreads();
    float bs = red[0];
#pragma unroll
    for (int w = 1; w < 8; w++) bs += red[w];

    const float inv = 1.0f / bs;
#pragma unroll
    for (int k = 0; k < 8; k++) p[tid + 256 * k] = v[k] * inv;
}

// ---------------- PV: attn_out[b,s,h*64+d] = sum_j P[bh,s,j] * V[bh,j,d] -
__global__ void __launch_bounds__(256) pv_kernel()
{
    __shared__ __align__(16) float As[8][128];
    __shared__ __align__(16) float Bs[8][64];
    const int tid = threadIdx.x;
    const int tx = tid & 15, ty = tid >> 4;
    const int i0 = blockIdx.x * 128;
    const int bh = blockIdx.y;

    const float* P = g_scores + (size_t)bh * S_ * S_;
    const float* V = g_vh + (size_t)bh * S_ * DK_;

    float acc[8][4] = {};
    const int arow = tid >> 1, aq = (tid & 1) * 4;
    const int brow = tid >> 4, bq = (tid & 15) * 4;   // tid<128 only

    for (int k0 = 0; k0 < S_; k0 += 8) {
        float4 av = *(const float4*)&P[(size_t)(i0 + arow) * S_ + k0 + aq];
        float4 bv;
        if (tid < 128) bv = *(const float4*)&V[(size_t)(k0 + brow) * DK_ + bq];
        __syncthreads();
        As[aq + 0][arow] = av.x; As[aq + 1][arow] = av.y;
        As[aq + 2][arow] = av.z; As[aq + 3][arow] = av.w;
        if (tid < 128) *(float4*)&Bs[brow][bq] = bv;
        __syncthreads();
#pragma unroll
        for (int kk = 0; kk < 8; kk++) {
            float a[8], bfr[4];
            *(float4*)&a[0]   = *(const float4*)&As[kk][ty * 4];
            *(float4*)&a[4]   = *(const float4*)&As[kk][64 + ty * 4];
            *(float4*)&bfr[0] = *(const float4*)&Bs[kk][tx * 4];
#pragma unroll
            for (int i = 0; i < 8; i++)
#pragma unroll
                for (int j = 0; j < 4; j++)
                    acc[i][j] = fmaf(a[i], bfr[j], acc[i][j]);
        }
    }

    const int b = bh >> 4, h = bh & 15;
#pragma unroll
    for (int i = 0; i < 8; i++) {
        const int r = (i < 4) ? (ty * 4 + i) : (60 + ty * 4 + i);
        float4 v = make_float4(acc[i][0], acc[i][1], acc[i][2], acc[i][3]);
        *(float4*)&g_attn[(size_t)(b * S_ + i0 + r) * D_ + h * 64 + tx * 4] = v;
    }
}

// ---------------- output projection: out = attn @ Wo + bo ---------------
__global__ void __launch_bounds__(256, 2) out_kernel(
    const float* __restrict__ W, const float* __restrict__ bias,
    float* __restrict__ out)
{
    __shared__ Tile t;
    float acc[8][8] = {};
    const int m0 = blockIdx.y * 128, n0 = blockIdx.x * 128;
    gemm128x128_k1024(g_attn, W, m0, n0, &t, acc);

    const int tx = threadIdx.x & 15, ty = threadIdx.x >> 4;
#pragma unroll
    for (int i = 0; i < 8; i++) {
        const int r = (i < 4) ? (ty * 4 + i) : (60 + ty * 4 + i);
        const size_t rowoff = (size_t)(m0 + r) * 1024;
#pragma unroll
        for (int jg = 0; jg < 2; jg++) {
            const int n = n0 + jg * 64 + tx * 4;
            float4 bb = *(const float4*)&bias[n];
            float4 v;
            v.x = acc[i][jg * 4 + 0] + bb.x;
            v.y = acc[i][jg * 4 + 1] + bb.y;
            v.z = acc[i][jg * 4 + 2] + bb.z;
            v.w = acc[i][jg * 4 + 3] + bb.w;
            *(float4*)&out[rowoff + n] = v;
        }
    }
}

// ------------------------------------------------------------------------
extern "C" void kernel_launch(void* const* d_in, const int* in_sizes, int n_in,
                              void* d_out, int out_size)
{
    const float* q    = (const float*)d_in[0];
    const float* k    = (const float*)d_in[1];
    const float* v    = (const float*)d_in[2];
    const int*   mask = (const int*)  d_in[3];
    const float* Wq   = (const float*)d_in[4];
    const float* bq   = (const float*)d_in[5];
    const float* Wk   = (const float*)d_in[6];
    const float* bk   = (const float*)d_in[7];
    const float* Wv   = (const float*)d_in[8];
    const float* bv   = (const float*)d_in[9];
    const float* Wo   = (const float*)d_in[10];
    const float* bo   = (const float*)d_in[11];
    float* out = (float*)d_out;

    dim3 gproj(D_ / 128, M_ / 128);          // (8, 32)
    proj_kernel<0><<<gproj, 256>>>(q, Wq, bq);
    proj_kernel<1><<<gproj, 256>>>(k, Wk, bk);
    proj_kernel<2><<<gproj, 256>>>(v, Wv, bv);

    dim3 gsc(S_ / 128, S_ / 128, BH_);       // (16, 16, 32)
    scores_kernel<<<gsc, 256>>>(mask);

    softmax_kernel<<<BH_ * S_, 256>>>();     // 65536 rows

    dim3 gpv(S_ / 128, BH_);                 // (16, 32)
    pv_kernel<<<gpv, 256>>>();

    out_kernel<<<gproj, 256>>>(Wo, bo, out);
}

// round 7
// speedup vs baseline: 1.3812x; 1.3812x over previous
#include <cuda_runtime.h>
#include <cstdint>

// Problem constants
#define B_   2
#define S_   2048
#define D_   1024
#define H_   16
#define DK_  64
#define BH_  (B_*H_)          // 32
#define M_   (B_*S_)          // 4096

// ---------------- scratch (device globals; no allocations allowed) -------
__device__ float g_qh[BH_ * S_ * DK_];        // [B*H, S, DK] head-major
__device__ float g_kh[BH_ * S_ * DK_];
__device__ float g_vh[BH_ * S_ * DK_];
__device__ float g_scores[(size_t)BH_ * S_ * S_];  // 512 MB
__device__ float g_attn[M_ * D_];             // [B,S,D]

// ---------------- tf32 helpers ------------------------------------------
__device__ __forceinline__ uint32_t f2tf(float f) {
    uint32_t u;
    asm("cvt.rna.tf32.f32 %0, %1;" : "=r"(u) : "f"(f));
    return u;
}

__device__ __forceinline__ void mma8(float* c, const uint32_t* a, const uint32_t* b) {
    asm volatile(
        "mma.sync.aligned.m16n8k8.row.col.f32.tf32.tf32.f32 "
        "{%0,%1,%2,%3}, {%4,%5,%6,%7}, {%8,%9}, {%0,%1,%2,%3};\n"
        : "+f"(c[0]), "+f"(c[1]), "+f"(c[2]), "+f"(c[3])
        : "r"(a[0]), "r"(a[1]), "r"(a[2]), "r"(a[3]),
          "r"(b[0]), "r"(b[1]));
}

// Padded strides (conflict-free fragment LDS):
//  A-style [row][k] stride 36: bank = (4*row + k)&31 -> distinct over a warp
//  B-style [k][n]  stride 136 (or 72): bank = (8*k + n)&31 -> distinct
#define SA_ 36
#define SB_ 136
#define SV_ 72

// ============================================================
//  Projection / output GEMM: C[128,128] = X[.,1024] @ W[1024,.] + b
//  512 threads, warp grid 4x4, warp tile 32x32 (2 m-mma x 4 n-mma)
//  DST: 0=g_qh 1=g_kh 2=g_vh 3=direct to `out` (source = g_attn)
// ============================================================
template<int DST>
__global__ void __launch_bounds__(512, 1) proj_tf32(
    const float* __restrict__ X, const float* __restrict__ W,
    const float* __restrict__ bias, float* __restrict__ out)
{
    __shared__ uint32_t As[128][SA_];
    __shared__ uint32_t Bs[32][SB_];

    // CRITICAL FIX vs R5: resolve device-global source INSIDE device code.
    const float* Xp = (DST == 3) ? (const float*)g_attn : X;

    const int tid  = threadIdx.x;
    const int warp = tid >> 5, lane = tid & 31;
    const int g = lane >> 2, tg = lane & 3;
    const int wm0 = (warp >> 2) * 32, wn0 = (warp & 3) * 32;
    const int m0 = blockIdx.y * 128, n0 = blockIdx.x * 128;

    float acc[2][4][4] = {};

    for (int k0 = 0; k0 < 1024; k0 += 32) {
        uint4 sa[2], sb[2];
#pragma unroll
        for (int i = 0; i < 2; i++) {
            int f = tid + 512 * i;
            int ar = f >> 3, aq = f & 7;
            float4 v = *(const float4*)(Xp + (size_t)(m0 + ar) * 1024 + k0 + aq * 4);
            sa[i] = make_uint4(f2tf(v.x), f2tf(v.y), f2tf(v.z), f2tf(v.w));
            int br = f >> 5, bq = f & 31;
            float4 w = *(const float4*)(W + (size_t)(k0 + br) * 1024 + n0 + bq * 4);
            sb[i] = make_uint4(f2tf(w.x), f2tf(w.y), f2tf(w.z), f2tf(w.w));
        }
        __syncthreads();
#pragma unroll
        for (int i = 0; i < 2; i++) {
            int f = tid + 512 * i;
            *(uint4*)&As[f >> 3][(f & 7) * 4]  = sa[i];
            *(uint4*)&Bs[f >> 5][(f & 31) * 4] = sb[i];
        }
        __syncthreads();
#pragma unroll
        for (int ks = 0; ks < 4; ks++) {
            const int kb = ks * 8;
            uint32_t a[2][4];
#pragma unroll
            for (int mi = 0; mi < 2; mi++) {
                int r = wm0 + mi * 16;
                a[mi][0] = As[r + g][kb + tg];
                a[mi][1] = As[r + g + 8][kb + tg];
                a[mi][2] = As[r + g][kb + tg + 4];
                a[mi][3] = As[r + g + 8][kb + tg + 4];
            }
#pragma unroll
            for (int ni = 0; ni < 4; ni++) {
                uint32_t b[2] = { Bs[kb + tg][wn0 + ni * 8 + g],
                                  Bs[kb + tg + 4][wn0 + ni * 8 + g] };
                mma8(acc[0][ni], a[0], b);
                mma8(acc[1][ni], a[1], b);
            }
        }
    }

    // epilogue
    float* dst = (DST == 0) ? g_qh : (DST == 1) ? g_kh : (DST == 2) ? g_vh : out;
#pragma unroll
    for (int mi = 0; mi < 2; mi++) {
#pragma unroll
        for (int rr = 0; rr < 2; rr++) {
            const int m = m0 + wm0 + mi * 16 + g + rr * 8;
#pragma unroll
            for (int ni = 0; ni < 4; ni++) {
                const int n = n0 + wn0 + ni * 8 + 2 * tg;
                float2 v;
                v.x = acc[mi][ni][rr * 2 + 0] + bias[n];
                v.y = acc[mi][ni][rr * 2 + 1] + bias[n + 1];
                if (DST == 3) {
                    *(float2*)&dst[(size_t)m * 1024 + n] = v;
                } else {
                    const int b = m >> 11, s = m & 2047;
                    const int h = n >> 6, d = n & 63;
                    *(float2*)&dst[((size_t)(b * H_ + h) * S_ + s) * DK_ + d] = v;
                }
            }
        }
    }
}

// ============================================================
//  Scores: P[bh,i,j] = (Q . K^T)/8, masked.  K staged A-style
//  (row-major [j][k]) -> B frags read transposed, conflict-free.
// ============================================================
__global__ void __launch_bounds__(512, 1) scores_tf32(const int* __restrict__ mask)
{
    __shared__ uint32_t As[128][SA_];
    __shared__ uint32_t Ks[128][SA_];
    __shared__ int smask[128];

    const int tid  = threadIdx.x;
    const int warp = tid >> 5, lane = tid & 31;
    const int g = lane >> 2, tg = lane & 3;
    const int wm0 = (warp >> 2) * 32, wn0 = (warp & 3) * 32;
    const int bh = blockIdx.z;
    const int i0 = blockIdx.y * 128, j0 = blockIdx.x * 128;
    const int bb = bh >> 4;

    const float* Q  = g_qh + (size_t)bh * S_ * DK_;
    const float* Kh = g_kh + (size_t)bh * S_ * DK_;

    if (tid < 128) smask[tid] = mask[bb * S_ + j0 + tid];

    float acc[2][4][4] = {};

    for (int k0 = 0; k0 < DK_; k0 += 32) {
        uint4 sa[2], sk[2];
#pragma unroll
        for (int i = 0; i < 2; i++) {
            int f = tid + 512 * i;
            int r = f >> 3, q = f & 7;
            float4 v = *(const float4*)(Q  + (size_t)(i0 + r) * DK_ + k0 + q * 4);
            float4 w = *(const float4*)(Kh + (size_t)(j0 + r) * DK_ + k0 + q * 4);
            sa[i] = make_uint4(f2tf(v.x), f2tf(v.y), f2tf(v.z), f2tf(v.w));
            sk[i] = make_uint4(f2tf(w.x), f2tf(w.y), f2tf(w.z), f2tf(w.w));
        }
        __syncthreads();
#pragma unroll
        for (int i = 0; i < 2; i++) {
            int f = tid + 512 * i;
            *(uint4*)&As[f >> 3][(f & 7) * 4] = sa[i];
            *(uint4*)&Ks[f >> 3][(f & 7) * 4] = sk[i];
        }
        __syncthreads();
#pragma unroll
        for (int ks = 0; ks < 4; ks++) {
            const int kb = ks * 8;
            uint32_t a[2][4];
#pragma unroll
            for (int mi = 0; mi < 2; mi++) {
                int r = wm0 + mi * 16;
                a[mi][0] = As[r + g][kb + tg];
                a[mi][1] = As[r + g + 8][kb + tg];
                a[mi][2] = As[r + g][kb + tg + 4];
                a[mi][3] = As[r + g + 8][kb + tg + 4];
            }
#pragma unroll
            for (int ni = 0; ni < 4; ni++) {
                const int n = wn0 + ni * 8 + g;
                uint32_t b[2] = { Ks[n][kb + tg], Ks[n][kb + tg + 4] };
                mma8(acc[0][ni], a[0], b);
                mma8(acc[1][ni], a[1], b);
            }
        }
    }

    float* P = g_scores + (size_t)bh * S_ * S_;
#pragma unroll
    for (int mi = 0; mi < 2; mi++) {
#pragma unroll
        for (int rr = 0; rr < 2; rr++) {
            const int i = i0 + wm0 + mi * 16 + g + rr * 8;
#pragma unroll
            for (int ni = 0; ni < 4; ni++) {
                const int jl = wn0 + ni * 8 + 2 * tg;
                float2 v;
                // reference semantics: positions with ORIGINAL mask != 0 -> -1e10
                v.x = smask[jl]     ? -1e10f : acc[mi][ni][rr * 2 + 0] * 0.125f;
                v.y = smask[jl + 1] ? -1e10f : acc[mi][ni][rr * 2 + 1] * 0.125f;
                *(float2*)&P[(size_t)i * S_ + j0 + jl] = v;
            }
        }
    }
}

// ---------------- row softmax over 2048 keys, in place ------------------
__global__ void __launch_bounds__(256) softmax_kernel()
{
    const int tid = threadIdx.x;
    float* p = g_scores + (size_t)blockIdx.x * S_;

    float v[8];
#pragma unroll
    for (int k = 0; k < 8; k++) v[k] = p[tid + 256 * k];

    float m = v[0];
#pragma unroll
    for (int k = 1; k < 8; k++) m = fmaxf(m, v[k]);
#pragma unroll
    for (int o = 16; o; o >>= 1) m = fmaxf(m, __shfl_xor_sync(0xffffffffu, m, o));

    __shared__ float red[8];
    if ((tid & 31) == 0) red[tid >> 5] = m;
    __syncthreads();
    float bm = red[0];
#pragma unroll
    for (int w = 1; w < 8; w++) bm = fmaxf(bm, red[w]);

    float s = 0.f;
#pragma unroll
    for (int k = 0; k < 8; k++) { v[k] = __expf(v[k] - bm); s += v[k]; }
#pragma unroll
    for (int o = 16; o; o >>= 1) s += __shfl_xor_sync(0xffffffffu, s, o);
    __syncthreads();
    if ((tid & 31) == 0) red[tid >> 5] = s;
    __syncthreads();
    float bs = red[0];
#pragma unroll
    for (int w = 1; w < 8; w++) bs += red[w];

    const float inv = 1.0f / bs;
#pragma unroll
    for (int k = 0; k < 8; k++) p[tid + 256 * k] = v[k] * inv;
}

// ============================================================
//  PV: attn[b,s,h*64+d] = sum_j P[bh,s,j] * V[bh,j,d]
//  Block 128(i) x 64(n), 512 threads, warp tile 32x16.
// ============================================================
__global__ void __launch_bounds__(512, 1) pv_tf32()
{
    __shared__ uint32_t As[128][SA_];
    __shared__ uint32_t Bs[32][SV_];

    const int tid  = threadIdx.x;
    const int warp = tid >> 5, lane = tid & 31;
    const int g = lane >> 2, tg = lane & 3;
    const int wm0 = (warp >> 2) * 32, wn0 = (warp & 3) * 16;
    const int i0 = blockIdx.x * 128;
    const int bh = blockIdx.y;

    const float* P = g_scores + (size_t)bh * S_ * S_;
    const float* V = g_vh + (size_t)bh * S_ * DK_;

    float acc[2][2][4] = {};

    for (int k0 = 0; k0 < S_; k0 += 32) {
        uint4 sa[2], sb;
#pragma unroll
        for (int i = 0; i < 2; i++) {
            int f = tid + 512 * i;
            int r = f >> 3, q = f & 7;
            float4 v = *(const float4*)(P + (size_t)(i0 + r) * S_ + k0 + q * 4);
            sa[i] = make_uint4(f2tf(v.x), f2tf(v.y), f2tf(v.z), f2tf(v.w));
        }
        {
            int br = tid >> 4, bq = tid & 15;
            float4 w = *(const float4*)(V + (size_t)(k0 + br) * DK_ + bq * 4);
            sb = make_uint4(f2tf(w.x), f2tf(w.y), f2tf(w.z), f2tf(w.w));
        }
        __syncthreads();
#pragma unroll
        for (int i = 0; i < 2; i++) {
            int f = tid + 512 * i;
            *(uint4*)&As[f >> 3][(f & 7) * 4] = sa[i];
        }
        *(uint4*)&Bs[tid >> 4][(tid & 15) * 4] = sb;
        __syncthreads();
#pragma unroll
        for (int ks = 0; ks < 4; ks++) {
            const int kb = ks * 8;
            uint32_t a[2][4];
#pragma unroll
            for (int mi = 0; mi < 2; mi++) {
                int r = wm0 + mi * 16;
                a[mi][0] = As[r + g][kb + tg];
                a[mi][1] = As[r + g + 8][kb + tg];
                a[mi][2] = As[r + g][kb + tg + 4];
                a[mi][3] = As[r + g + 8][kb + tg + 4];
            }
#pragma unroll
            for (int ni = 0; ni < 2; ni++) {
                uint32_t b[2] = { Bs[kb + tg][wn0 + ni * 8 + g],
                                  Bs[kb + tg + 4][wn0 + ni * 8 + g] };
                mma8(acc[0][ni], a[0], b);
                mma8(acc[1][ni], a[1], b);
            }
        }
    }

    const int bb = bh >> 4, h = bh & 15;
#pragma unroll
    for (int mi = 0; mi < 2; mi++) {
#pragma unroll
        for (int rr = 0; rr < 2; rr++) {
            const int i = i0 + wm0 + mi * 16 + g + rr * 8;
#pragma unroll
            for (int ni = 0; ni < 2; ni++) {
                const int n = wn0 + ni * 8 + 2 * tg;
                float2 v;
                v.x = acc[mi][ni][rr * 2 + 0];
                v.y = acc[mi][ni][rr * 2 + 1];
                *(float2*)&g_attn[(size_t)(bb * S_ + i) * D_ + h * 64 + n] = v;
            }
        }
    }
}

// ------------------------------------------------------------------------
extern "C" void kernel_launch(void* const* d_in, const int* in_sizes, int n_in,
                              void* d_out, int out_size)
{
    const float* q    = (const float*)d_in[0];
    const float* k    = (const float*)d_in[1];
    const float* v    = (const float*)d_in[2];
    const int*   mask = (const int*)  d_in[3];
    const float* Wq   = (const float*)d_in[4];
    const float* bq   = (const float*)d_in[5];
    const float* Wk   = (const float*)d_in[6];
    const float* bk   = (const float*)d_in[7];
    const float* Wv   = (const float*)d_in[8];
    const float* bv   = (const float*)d_in[9];
    const float* Wo   = (const float*)d_in[10];
    const float* bo   = (const float*)d_in[11];
    float* out = (float*)d_out;

    dim3 gproj(D_ / 128, M_ / 128);          // (8, 32)
    proj_tf32<0><<<gproj, 512>>>(q, Wq, bq, nullptr);
    proj_tf32<1><<<gproj, 512>>>(k, Wk, bk, nullptr);
    proj_tf32<2><<<gproj, 512>>>(v, Wv, bv, nullptr);

    dim3 gsc(S_ / 128, S_ / 128, BH_);       // (16, 16, 32)
    scores_tf32<<<gsc, 512>>>(mask);

    softmax_kernel<<<BH_ * S_, 256>>>();     // 65536 rows

    dim3 gpv(S_ / 128, BH_);                 // (16, 32)
    pv_tf32<<<gpv, 512>>>();

    // Source for the out-projection (g_attn) is resolved inside the kernel.
    proj_tf32<3><<<gproj, 512>>>(nullptr, Wo, bo, out);
}

// round 8
// speedup vs baseline: 2.4745x; 1.7915x over previous
#include <cuda_runtime.h>
#include <cstdint>

// Problem constants
#define B_   2
#define S_   2048
#define D_   1024
#define H_   16
#define DK_  64
#define BH_  (B_*H_)          // 32
#define M_   (B_*S_)          // 4096

// ---------------- scratch (device globals; no allocations allowed) -------
__device__ float g_qh[BH_ * S_ * DK_];        // [B*H, S, DK] head-major
__device__ float g_kh[BH_ * S_ * DK_];
__device__ float g_vh[BH_ * S_ * DK_];
__device__ float g_attn[M_ * D_];             // [B,S,D]

// ---------------- tf32 helpers ------------------------------------------
__device__ __forceinline__ uint32_t f2tf(float f) {
    uint32_t u;
    asm("cvt.rna.tf32.f32 %0, %1;" : "=r"(u) : "f"(f));
    return u;
}

__device__ __forceinline__ void mma8(float* c, const uint32_t* a, const uint32_t* b) {
    asm volatile(
        "mma.sync.aligned.m16n8k8.row.col.f32.tf32.tf32.f32 "
        "{%0,%1,%2,%3}, {%4,%5,%6,%7}, {%8,%9}, {%0,%1,%2,%3};\n"
        : "+f"(c[0]), "+f"(c[1]), "+f"(c[2]), "+f"(c[3])
        : "r"(a[0]), "r"(a[1]), "r"(a[2]), "r"(a[3]),
          "r"(b[0]), "r"(b[1]));
}

// Padded strides (conflict-free fragment LDS):
//  A-style [row][k]: stride ≡ 4 (mod 32)  -> bank (4*row+k)&31 distinct
//  B-style [k][n]:   stride ≡ 8 (mod 32)  -> bank (8*k+n)&31 distinct
#define SA_ 36
#define SB_ 136

// ============================================================
//  Projection / output GEMM  (UNCHANGED from R7 — proven)
//  C[128,128] = X[.,1024] @ W[1024,.] + b ; 512 thr, warp 4x4
//  DST: 0=g_qh 1=g_kh 2=g_vh 3=direct to `out` (source = g_attn)
// ============================================================
template<int DST>
__global__ void __launch_bounds__(512, 1) proj_tf32(
    const float* __restrict__ X, const float* __restrict__ W,
    const float* __restrict__ bias, float* __restrict__ out)
{
    __shared__ uint32_t As[128][SA_];
    __shared__ uint32_t Bs[32][SB_];

    const float* Xp = (DST == 3) ? (const float*)g_attn : X;

    const int tid  = threadIdx.x;
    const int warp = tid >> 5, lane = tid & 31;
    const int g = lane >> 2, tg = lane & 3;
    const int wm0 = (warp >> 2) * 32, wn0 = (warp & 3) * 32;
    const int m0 = blockIdx.y * 128, n0 = blockIdx.x * 128;

    float acc[2][4][4] = {};

    for (int k0 = 0; k0 < 1024; k0 += 32) {
        uint4 sa[2], sb[2];
#pragma unroll
        for (int i = 0; i < 2; i++) {
            int f = tid + 512 * i;
            int ar = f >> 3, aq = f & 7;
            float4 v = *(const float4*)(Xp + (size_t)(m0 + ar) * 1024 + k0 + aq * 4);
            sa[i] = make_uint4(f2tf(v.x), f2tf(v.y), f2tf(v.z), f2tf(v.w));
            int br = f >> 5, bq = f & 31;
            float4 w = *(const float4*)(W + (size_t)(k0 + br) * 1024 + n0 + bq * 4);
            sb[i] = make_uint4(f2tf(w.x), f2tf(w.y), f2tf(w.z), f2tf(w.w));
        }
        __syncthreads();
#pragma unroll
        for (int i = 0; i < 2; i++) {
            int f = tid + 512 * i;
            *(uint4*)&As[f >> 3][(f & 7) * 4]  = sa[i];
            *(uint4*)&Bs[f >> 5][(f & 31) * 4] = sb[i];
        }
        __syncthreads();
#pragma unroll
        for (int ks = 0; ks < 4; ks++) {
            const int kb = ks * 8;
            uint32_t a[2][4];
#pragma unroll
            for (int mi = 0; mi < 2; mi++) {
                int r = wm0 + mi * 16;
                a[mi][0] = As[r + g][kb + tg];
                a[mi][1] = As[r + g + 8][kb + tg];
                a[mi][2] = As[r + g][kb + tg + 4];
                a[mi][3] = As[r + g + 8][kb + tg + 4];
            }
#pragma unroll
            for (int ni = 0; ni < 4; ni++) {
                uint32_t b[2] = { Bs[kb + tg][wn0 + ni * 8 + g],
                                  Bs[kb + tg + 4][wn0 + ni * 8 + g] };
                mma8(acc[0][ni], a[0], b);
                mma8(acc[1][ni], a[1], b);
            }
        }
    }

    float* dst = (DST == 0) ? g_qh : (DST == 1) ? g_kh : (DST == 2) ? g_vh : out;
#pragma unroll
    for (int mi = 0; mi < 2; mi++) {
#pragma unroll
        for (int rr = 0; rr < 2; rr++) {
            const int m = m0 + wm0 + mi * 16 + g + rr * 8;
#pragma unroll
            for (int ni = 0; ni < 4; ni++) {
                const int n = n0 + wn0 + ni * 8 + 2 * tg;
                float2 v;
                v.x = acc[mi][ni][rr * 2 + 0] + bias[n];
                v.y = acc[mi][ni][rr * 2 + 1] + bias[n + 1];
                if (DST == 3) {
                    *(float2*)&dst[(size_t)m * 1024 + n] = v;
                } else {
                    const int b = m >> 11, s = m & 2047;
                    const int h = n >> 6, d = n & 63;
                    *(float2*)&dst[((size_t)(b * H_ + h) * S_ + s) * DK_ + d] = v;
                }
            }
        }
    }
}

// ============================================================
//  Fused flash attention: softmax(QK^T/8 + mask) @ V -> g_attn
//  Block: 64 query rows of one head. 256 threads, 8 warps (2x4).
//  Key loop: 32 tiles of 64 keys. Online softmax, O in registers.
//  P staged via smem (aliases the K tile) for mma A-fragments.
// ============================================================
struct FlashSmem {
    uint32_t Qs[64][68];    // Q tile, A-style  (68 ≡ 4 mod 32)
    uint32_t KPs[64][68];   // K tile; reused as P tile after stats
    uint32_t Vs[64][72];    // V tile, B-style  (72 ≡ 8 mod 32)
    float sredm[4][64];     // per-warp-col partial row max
    float sreds[4][64];     // per-warp-col partial row sum
    int   smask[64];
};

__global__ void __launch_bounds__(256, 2) flash_tf32(const int* __restrict__ mask)
{
    extern __shared__ char smem_raw[];
    FlashSmem& sm = *reinterpret_cast<FlashSmem*>(smem_raw);

    const int tid  = threadIdx.x;
    const int warp = tid >> 5, lane = tid & 31;
    const int g = lane >> 2, tg = lane & 3;
    const int wm = (warp >> 2) * 32;     // 0 or 32  (m band)
    const int wn = (warp & 3) * 16;      // 0/16/32/48 (n band)
    const int wc = warp & 3;             // warp column id
    const int i0 = blockIdx.x * 64;
    const int bh = blockIdx.y;
    const int bb = bh >> 4, h = bh & 15;

    const float* Q = g_qh + (size_t)bh * S_ * DK_;
    const float* K = g_kh + (size_t)bh * S_ * DK_;
    const float* V = g_vh + (size_t)bh * S_ * DK_;

    // ---- stage Q tile once: 64 x 64 = 1024 float4, 4 per thread ----
#pragma unroll
    for (int i = 0; i < 4; i++) {
        int f = tid + 256 * i;
        int r = f >> 4, q4 = f & 15;
        float4 v = *(const float4*)(Q + (size_t)(i0 + r) * DK_ + q4 * 4);
        *(uint4*)&sm.Qs[r][q4 * 4] =
            make_uint4(f2tf(v.x), f2tf(v.y), f2tf(v.z), f2tf(v.w));
    }

    float m_st[2][2], l_st[2][2];
    float acc_o[2][2][4] = {};
#pragma unroll
    for (int mi = 0; mi < 2; mi++)
#pragma unroll
        for (int rr = 0; rr < 2; rr++) { m_st[mi][rr] = -1e30f; l_st[mi][rr] = 0.f; }

    for (int t = 0; t < S_ / 64; t++) {
        const int j0 = t * 64;

        // ---- stage K (A-style) and V (B-style) tiles + mask ----
        __syncthreads();   // protect KPs/Vs/smask from previous iteration readers
#pragma unroll
        for (int i = 0; i < 4; i++) {
            int f = tid + 256 * i;
            int r = f >> 4, q4 = f & 15;
            float4 kv = *(const float4*)(K + (size_t)(j0 + r) * DK_ + q4 * 4);
            float4 vv = *(const float4*)(V + (size_t)(j0 + r) * DK_ + q4 * 4);
            *(uint4*)&sm.KPs[r][q4 * 4] =
                make_uint4(f2tf(kv.x), f2tf(kv.y), f2tf(kv.z), f2tf(kv.w));
            *(uint4*)&sm.Vs[r][q4 * 4] =
                make_uint4(f2tf(vv.x), f2tf(vv.y), f2tf(vv.z), f2tf(vv.w));
        }
        if (tid < 64) sm.smask[tid] = mask[bb * S_ + j0 + tid];
        __syncthreads();

        // ---- S = Q . K^T  (64x64 tile; this warp: 32x16) ----
        float acc_s[2][2][4] = {};
#pragma unroll
        for (int ks = 0; ks < 8; ks++) {
            const int kb = ks * 8;
            uint32_t a[2][4];
#pragma unroll
            for (int mi = 0; mi < 2; mi++) {
                int r = wm + mi * 16;
                a[mi][0] = sm.Qs[r + g][kb + tg];
                a[mi][1] = sm.Qs[r + g + 8][kb + tg];
                a[mi][2] = sm.Qs[r + g][kb + tg + 4];
                a[mi][3] = sm.Qs[r + g + 8][kb + tg + 4];
            }
#pragma unroll
            for (int ni = 0; ni < 2; ni++) {
                const int n = wn + ni * 8 + g;
                uint32_t b[2] = { sm.KPs[n][kb + tg], sm.KPs[n][kb + tg + 4] };
                mma8(acc_s[0][ni], a[0], b);
                mma8(acc_s[1][ni], a[1], b);
            }
        }

        // ---- scale + mask, partial row max ----
#pragma unroll
        for (int mi = 0; mi < 2; mi++) {
#pragma unroll
            for (int rr = 0; rr < 2; rr++) {
                float mx = -1e30f;
#pragma unroll
                for (int ni = 0; ni < 2; ni++) {
#pragma unroll
                    for (int c = 0; c < 2; c++) {
                        const int col = wn + ni * 8 + 2 * tg + c;
                        float s = acc_s[mi][ni][rr * 2 + c];
                        s = sm.smask[col] ? -1e10f : s * 0.125f;
                        acc_s[mi][ni][rr * 2 + c] = s;
                        mx = fmaxf(mx, s);
                    }
                }
                mx = fmaxf(mx, __shfl_xor_sync(0xffffffffu, mx, 1));
                mx = fmaxf(mx, __shfl_xor_sync(0xffffffffu, mx, 2));
                if (tg == 0) sm.sredm[wc][wm + mi * 16 + rr * 8 + g] = mx;
            }
        }
        __syncthreads();   // all S-mma done -> KPs free for P; sredm ready

        // ---- online softmax update; write P over KPs ----
        float alpha[2][2];
#pragma unroll
        for (int mi = 0; mi < 2; mi++) {
#pragma unroll
            for (int rr = 0; rr < 2; rr++) {
                const int row = wm + mi * 16 + rr * 8 + g;
                float tm = fmaxf(fmaxf(sm.sredm[0][row], sm.sredm[1][row]),
                                 fmaxf(sm.sredm[2][row], sm.sredm[3][row]));
                float mn = fmaxf(m_st[mi][rr], tm);
                alpha[mi][rr] = __expf(m_st[mi][rr] - mn);
                m_st[mi][rr] = mn;
                float ps = 0.f;
#pragma unroll
                for (int ni = 0; ni < 2; ni++) {
#pragma unroll
                    for (int c = 0; c < 2; c++) {
                        float p = __expf(acc_s[mi][ni][rr * 2 + c] - mn);
                        acc_s[mi][ni][rr * 2 + c] = p;
                        ps += p;
                    }
                }
                ps += __shfl_xor_sync(0xffffffffu, ps, 1);
                ps += __shfl_xor_sync(0xffffffffu, ps, 2);
                if (tg == 0) sm.sreds[wc][row] = ps;
#pragma unroll
                for (int ni = 0; ni < 2; ni++) {
                    uint2 u = make_uint2(f2tf(acc_s[mi][ni][rr * 2 + 0]),
                                         f2tf(acc_s[mi][ni][rr * 2 + 1]));
                    *(uint2*)&sm.KPs[row][wn + ni * 8 + 2 * tg] = u;
                }
            }
        }
        // rescale O accumulator
#pragma unroll
        for (int mi = 0; mi < 2; mi++)
#pragma unroll
            for (int ni = 0; ni < 2; ni++)
#pragma unroll
                for (int e = 0; e < 4; e++)
                    acc_o[mi][ni][e] *= alpha[mi][e >> 1];
        __syncthreads();   // P tile + sreds complete

        // ---- l update ----
#pragma unroll
        for (int mi = 0; mi < 2; mi++) {
#pragma unroll
            for (int rr = 0; rr < 2; rr++) {
                const int row = wm + mi * 16 + rr * 8 + g;
                float ts = (sm.sreds[0][row] + sm.sreds[1][row]) +
                           (sm.sreds[2][row] + sm.sreds[3][row]);
                l_st[mi][rr] = l_st[mi][rr] * alpha[mi][rr] + ts;
            }
        }

        // ---- O += P . V   (A = P[64 rows x 64 k], B = V[64 k x 64 d]) ----
#pragma unroll
        for (int ks = 0; ks < 8; ks++) {
            const int kb = ks * 8;
            uint32_t a[2][4];
#pragma unroll
            for (int mi = 0; mi < 2; mi++) {
                int r = wm + mi * 16;
                a[mi][0] = sm.KPs[r + g][kb + tg];
                a[mi][1] = sm.KPs[r + g + 8][kb + tg];
                a[mi][2] = sm.KPs[r + g][kb + tg + 4];
                a[mi][3] = sm.KPs[r + g + 8][kb + tg + 4];
            }
#pragma unroll
            for (int ni = 0; ni < 2; ni++) {
                uint32_t b[2] = { sm.Vs[kb + tg][wn + ni * 8 + g],
                                  sm.Vs[kb + tg + 4][wn + ni * 8 + g] };
                mma8(acc_o[0][ni], a[0], b);
                mma8(acc_o[1][ni], a[1], b);
            }
        }
        // next-iteration staging is protected by the loop-top __syncthreads
    }

    // ---- epilogue: O /= l, scatter to g_attn[b, s, h*64 + d] ----
#pragma unroll
    for (int mi = 0; mi < 2; mi++) {
#pragma unroll
        for (int rr = 0; rr < 2; rr++) {
            const int row = wm + mi * 16 + rr * 8 + g;
            const float inv = 1.0f / l_st[mi][rr];
#pragma unroll
            for (int ni = 0; ni < 2; ni++) {
                const int d = wn + ni * 8 + 2 * tg;
                float2 o;
                o.x = acc_o[mi][ni][rr * 2 + 0] * inv;
                o.y = acc_o[mi][ni][rr * 2 + 1] * inv;
                *(float2*)&g_attn[(size_t)(bb * S_ + i0 + row) * D_ + h * 64 + d] = o;
            }
        }
    }
}

// ------------------------------------------------------------------------
extern "C" void kernel_launch(void* const* d_in, const int* in_sizes, int n_in,
                              void* d_out, int out_size)
{
    const float* q    = (const float*)d_in[0];
    const float* k    = (const float*)d_in[1];
    const float* v    = (const float*)d_in[2];
    const int*   mask = (const int*)  d_in[3];
    const float* Wq   = (const float*)d_in[4];
    const float* bq   = (const float*)d_in[5];
    const float* Wk   = (const float*)d_in[6];
    const float* bk   = (const float*)d_in[7];
    const float* Wv   = (const float*)d_in[8];
    const float* bv   = (const float*)d_in[9];
    const float* Wo   = (const float*)d_in[10];
    const float* bo   = (const float*)d_in[11];
    float* out = (float*)d_out;

    // opt-in to >48KB dynamic smem for the flash kernel (idempotent, host-side)
    cudaFuncSetAttribute(flash_tf32,
                         cudaFuncAttributeMaxDynamicSharedMemorySize,
                         (int)sizeof(FlashSmem));

    dim3 gproj(D_ / 128, M_ / 128);          // (8, 32)
    proj_tf32<0><<<gproj, 512>>>(q, Wq, bq, nullptr);
    proj_tf32<1><<<gproj, 512>>>(k, Wk, bk, nullptr);
    proj_tf32<2><<<gproj, 512>>>(v, Wv, bv, nullptr);

    dim3 gfl(S_ / 64, BH_);                  // (32, 32) = 1024 blocks
    flash_tf32<<<gfl, 256, sizeof(FlashSmem)>>>(mask);

    proj_tf32<3><<<gproj, 512>>>(nullptr, Wo, bo, out);
}

// round 12
// speedup vs baseline: 2.6183x; 1.0581x over previous
#include <cuda_runtime.h>
#include <cstdint>

// Problem constants
#define B_   2
#define S_   2048
#define D_   1024
#define H_   16
#define DK_  64
#define BH_  (B_*H_)          // 32
#define M_   (B_*S_)          // 4096

// ---------------- scratch (device globals; no allocations allowed) -------
__device__ float g_qh[BH_ * S_ * DK_];        // [B*H, S, DK] head-major (Q pre-scaled by 1/8)
__device__ float g_kh[BH_ * S_ * DK_];
__device__ float g_vh[BH_ * S_ * DK_];
__device__ float g_attn[M_ * D_];             // [B,S,D]

// ---------------- tf32 helpers ------------------------------------------
__device__ __forceinline__ uint32_t f2tf(float f) {
    uint32_t u;
    asm("cvt.rna.tf32.f32 %0, %1;" : "=r"(u) : "f"(f));
    return u;
}

__device__ __forceinline__ void mma8(float* c, const uint32_t* a, const uint32_t* b) {
    asm volatile(
        "mma.sync.aligned.m16n8k8.row.col.f32.tf32.tf32.f32 "
        "{%0,%1,%2,%3}, {%4,%5,%6,%7}, {%8,%9}, {%0,%1,%2,%3};\n"
        : "+f"(c[0]), "+f"(c[1]), "+f"(c[2]), "+f"(c[3])
        : "r"(a[0]), "r"(a[1]), "r"(a[2]), "r"(a[3]),
          "r"(b[0]), "r"(b[1]));
}

// Padded strides (conflict-free fragment LDS):
//  A-style [row][k]: stride ≡ 4 (mod 32) -> bank (4*row+k)&31 distinct
//  B-style [k][n]:   stride ≡ 8 (mod 32) -> bank (8*k+n)&31 distinct
#define SA_ 36
#define SB_ 136

// ============================================================
//  Projection / output GEMM, ping-pong double buffered.
//  C[128,128] = X[.,1024] @ W[1024,.] + b ; 512 thr, warp 4x4.
//  DST: 0=g_qh(scaled 1/8) 1=g_kh 2=g_vh 3=direct to `out` (src g_attn)
// ============================================================
struct ProjSmem {
    uint32_t As[2][128][SA_];
    uint32_t Bs[2][32][SB_];
};

template<int DST>
__global__ void __launch_bounds__(512, 1) proj_tf32(
    const float* __restrict__ X, const float* __restrict__ W,
    const float* __restrict__ bias, float* __restrict__ out)
{
    extern __shared__ char smraw[];
    ProjSmem& sm = *reinterpret_cast<ProjSmem*>(smraw);

    const float* Xp = (DST == 3) ? (const float*)g_attn : X;

    const int tid  = threadIdx.x;
    const int warp = tid >> 5, lane = tid & 31;
    const int g = lane >> 2, tg = lane & 3;
    const int wm0 = (warp >> 2) * 32, wn0 = (warp & 3) * 32;
    const int m0 = blockIdx.y * 128, n0 = blockIdx.x * 128;

    const int ar = tid >> 3, aq = tid & 7;      // A stage: row, k-quad
    const int br = tid >> 5, bq = tid & 31;     // B stage: k-row, n-quad
    const float* Abase = Xp + (size_t)(m0 + ar) * 1024 + aq * 4;
    const float* A2    = Xp + (size_t)(m0 + 64 + ar) * 1024 + aq * 4;
    const float* Bbase = W + (size_t)br * 1024 + n0 + bq * 4;
    const float* B2    = W + (size_t)(br + 16) * 1024 + n0 + bq * 4;

    uint4 sa[2], sb[2];
    auto ldglobal = [&](int k0) {
        float4 v0 = *(const float4*)(Abase + k0);
        float4 v1 = *(const float4*)(A2 + k0);
        sa[0] = make_uint4(f2tf(v0.x), f2tf(v0.y), f2tf(v0.z), f2tf(v0.w));
        sa[1] = make_uint4(f2tf(v1.x), f2tf(v1.y), f2tf(v1.z), f2tf(v1.w));
        float4 w0 = *(const float4*)(Bbase + (size_t)k0 * 1024);
        float4 w1 = *(const float4*)(B2 + (size_t)k0 * 1024);
        sb[0] = make_uint4(f2tf(w0.x), f2tf(w0.y), f2tf(w0.z), f2tf(w0.w));
        sb[1] = make_uint4(f2tf(w1.x), f2tf(w1.y), f2tf(w1.z), f2tf(w1.w));
    };
    auto store = [&](int p) {
        *(uint4*)&sm.As[p][ar][aq * 4]       = sa[0];
        *(uint4*)&sm.As[p][64 + ar][aq * 4]  = sa[1];
        *(uint4*)&sm.Bs[p][br][bq * 4]       = sb[0];
        *(uint4*)&sm.Bs[p][16 + br][bq * 4]  = sb[1];
    };

    float acc[2][4][4] = {};

    ldglobal(0);
    store(0);
    __syncthreads();

    int p = 0;
    for (int k0 = 0; k0 < 1024; k0 += 32) {
        const bool more = (k0 + 32 < 1024);
        if (more) ldglobal(k0 + 32);
#pragma unroll
        for (int ks = 0; ks < 4; ks++) {
            const int kb = ks * 8;
            uint32_t a[2][4];
#pragma unroll
            for (int mi = 0; mi < 2; mi++) {
                int r = wm0 + mi * 16;
                a[mi][0] = sm.As[p][r + g][kb + tg];
                a[mi][1] = sm.As[p][r + g + 8][kb + tg];
                a[mi][2] = sm.As[p][r + g][kb + tg + 4];
                a[mi][3] = sm.As[p][r + g + 8][kb + tg + 4];
            }
#pragma unroll
            for (int ni = 0; ni < 4; ni++) {
                uint32_t b[2] = { sm.Bs[p][kb + tg][wn0 + ni * 8 + g],
                                  sm.Bs[p][kb + tg + 4][wn0 + ni * 8 + g] };
                mma8(acc[0][ni], a[0], b);
                mma8(acc[1][ni], a[1], b);
            }
        }
        if (more) store(p ^ 1);
        __syncthreads();
        p ^= 1;
    }

    float* dst = (DST == 0) ? g_qh : (DST == 1) ? g_kh : (DST == 2) ? g_vh : out;
#pragma unroll
    for (int mi = 0; mi < 2; mi++) {
#pragma unroll
        for (int rr = 0; rr < 2; rr++) {
            const int m = m0 + wm0 + mi * 16 + g + rr * 8;
#pragma unroll
            for (int ni = 0; ni < 4; ni++) {
                const int n = n0 + wn0 + ni * 8 + 2 * tg;
                float2 v;
                v.x = acc[mi][ni][rr * 2 + 0] + bias[n];
                v.y = acc[mi][ni][rr * 2 + 1] + bias[n + 1];
                if (DST == 0) { v.x *= 0.125f; v.y *= 0.125f; }  // fold 1/sqrt(DK)
                if (DST == 3) {
                    *(float2*)&dst[(size_t)m * 1024 + n] = v;
                } else {
                    const int b = m >> 11, s = m & 2047;
                    const int h = n >> 6, d = n & 63;
                    *(float2*)&dst[((size_t)(b * H_ + h) * S_ + s) * DK_ + d] = v;
                }
            }
        }
    }
}

// ============================================================
//  Fused flash attention: softmax(QK^T + mask) @ V -> g_attn
//  Block: 64 q rows of one head, 256 threads (8 warps).
//  Key loop: 16 tiles of 128 keys. Online softmax, O in registers.
//  S-phase: warp grid 2m x 4n (warp 32x32).
//  O-phase: warp grid 2m x 4n over d (warp 32x16).
//  P (64 x 128, stride 132) overlays the K tile (128 x 68).
// ============================================================
#define SP_ 132

struct FlashSmem {
    uint32_t Qs[64][68];
    uint32_t KP[128][68];    // K tile; reused as P[64][SP_] after stats
    uint32_t Vs[128][72];    // V tile, B-style
    float sredm[4][64];
    float sreds[4][64];
    int   smask[128];
};

__global__ void __launch_bounds__(256, 2) flash_tf32(const int* __restrict__ mask)
{
    extern __shared__ char smem_raw[];
    FlashSmem& sm = *reinterpret_cast<FlashSmem*>(smem_raw);
    uint32_t* Pb = &sm.KP[0][0];    // P[row][k] at Pb[row*SP_ + k]

    const int tid  = threadIdx.x;
    const int warp = tid >> 5, lane = tid & 31;
    const int g = lane >> 2, tg = lane & 3;
    const int wr = warp >> 2, wc = warp & 3;
    const int wm = wr * 32;
    const int i0 = blockIdx.x * 64;
    const int bh = blockIdx.y;
    const int bb = bh >> 4, h = bh & 15;

    const float* Q = g_qh + (size_t)bh * S_ * DK_;
    const float* K = g_kh + (size_t)bh * S_ * DK_;
    const float* V = g_vh + (size_t)bh * S_ * DK_;

    // ---- stage Q tile once (already scaled by 1/8) ----
#pragma unroll
    for (int i = 0; i < 4; i++) {
        int f = tid + 256 * i;
        int r = f >> 4, q4 = f & 15;
        float4 v = *(const float4*)(Q + (size_t)(i0 + r) * DK_ + q4 * 4);
        *(uint4*)&sm.Qs[r][q4 * 4] =
            make_uint4(f2tf(v.x), f2tf(v.y), f2tf(v.z), f2tf(v.w));
    }

    float m_st[2][2], l_st[2][2];
    float acc_o[2][2][4] = {};
#pragma unroll
    for (int mi = 0; mi < 2; mi++)
#pragma unroll
        for (int rr = 0; rr < 2; rr++) { m_st[mi][rr] = -1e30f; l_st[mi][rr] = 0.f; }

    for (int t = 0; t < S_ / 128; t++) {
        const int j0 = t * 128;

        __syncthreads();   // previous tile's readers of KP/Vs/smask done
        // ---- stage K (A-style [key][k]) and V (B-style [k][d]) ----
#pragma unroll
        for (int i = 0; i < 8; i++) {
            int f = tid + 256 * i;
            int r = f >> 4, q4 = f & 15;
            float4 kv = *(const float4*)(K + (size_t)(j0 + r) * DK_ + q4 * 4);
            *(uint4*)&sm.KP[r][q4 * 4] =
                make_uint4(f2tf(kv.x), f2tf(kv.y), f2tf(kv.z), f2tf(kv.w));
            float4 vv = *(const float4*)(V + (size_t)(j0 + r) * DK_ + q4 * 4);
            *(uint4*)&sm.Vs[r][q4 * 4] =
                make_uint4(f2tf(vv.x), f2tf(vv.y), f2tf(vv.z), f2tf(vv.w));
        }
        if (tid < 128) sm.smask[tid] = mask[bb * S_ + j0 + tid];
        __syncthreads();

        // ---- S = Q.K^T ; this warp: rows [wm,wm+32), keys [wc*32,+32) ----
        float acc_s[2][4][4] = {};
#pragma unroll
        for (int ks = 0; ks < 8; ks++) {
            const int kb = ks * 8;
            uint32_t a[2][4];
#pragma unroll
            for (int mi = 0; mi < 2; mi++) {
                int r = wm + mi * 16;
                a[mi][0] = sm.Qs[r + g][kb + tg];
                a[mi][1] = sm.Qs[r + g + 8][kb + tg];
                a[mi][2] = sm.Qs[r + g][kb + tg + 4];
                a[mi][3] = sm.Qs[r + g + 8][kb + tg + 4];
            }
#pragma unroll
            for (int ni = 0; ni < 4; ni++) {
                const int n = wc * 32 + ni * 8 + g;
                uint32_t b[2] = { sm.KP[n][kb + tg], sm.KP[n][kb + tg + 4] };
                mma8(acc_s[0][ni], a[0], b);
                mma8(acc_s[1][ni], a[1], b);
            }
        }

        // ---- mask + per-warp-col row max ----
#pragma unroll
        for (int mi = 0; mi < 2; mi++) {
#pragma unroll
            for (int rr = 0; rr < 2; rr++) {
                float mx = -1e30f;
#pragma unroll
                for (int ni = 0; ni < 4; ni++) {
#pragma unroll
                    for (int c = 0; c < 2; c++) {
                        const int col = wc * 32 + ni * 8 + 2 * tg + c;
                        float s = acc_s[mi][ni][rr * 2 + c];
                        s = sm.smask[col] ? -1e10f : s;
                        acc_s[mi][ni][rr * 2 + c] = s;
                        mx = fmaxf(mx, s);
                    }
                }
                mx = fmaxf(mx, __shfl_xor_sync(0xffffffffu, mx, 1));
                mx = fmaxf(mx, __shfl_xor_sync(0xffffffffu, mx, 2));
                if (tg == 0) sm.sredm[wc][wm + mi * 16 + rr * 8 + g] = mx;
            }
        }
        __syncthreads();   // S-mma done (KP free for P); sredm ready

        // ---- online softmax update; write P over KP ----
        float alpha[2][2];
#pragma unroll
        for (int mi = 0; mi < 2; mi++) {
#pragma unroll
            for (int rr = 0; rr < 2; rr++) {
                const int row = wm + mi * 16 + rr * 8 + g;
                float tm = fmaxf(fmaxf(sm.sredm[0][row], sm.sredm[1][row]),
                                 fmaxf(sm.sredm[2][row], sm.sredm[3][row]));
                float mn = fmaxf(m_st[mi][rr], tm);
                alpha[mi][rr] = __expf(m_st[mi][rr] - mn);
                m_st[mi][rr] = mn;
                float ps = 0.f;
#pragma unroll
                for (int ni = 0; ni < 4; ni++) {
#pragma unroll
                    for (int c = 0; c < 2; c++) {
                        float pv = __expf(acc_s[mi][ni][rr * 2 + c] - mn);
                        acc_s[mi][ni][rr * 2 + c] = pv;
                        ps += pv;
                    }
                }
                ps += __shfl_xor_sync(0xffffffffu, ps, 1);
                ps += __shfl_xor_sync(0xffffffffu, ps, 2);
                if (tg == 0) sm.sreds[wc][row] = ps;
#pragma unroll
                for (int ni = 0; ni < 4; ni++) {
                    uint2 u = make_uint2(f2tf(acc_s[mi][ni][rr * 2 + 0]),
                                         f2tf(acc_s[mi][ni][rr * 2 + 1]));
                    *(uint2*)&Pb[row * SP_ + wc * 32 + ni * 8 + 2 * tg] = u;
                }
            }
        }
        // rescale O accumulator
#pragma unroll
        for (int mi = 0; mi < 2; mi++)
#pragma unroll
            for (int ni = 0; ni < 2; ni++)
#pragma unroll
                for (int e = 0; e < 4; e++)
                    acc_o[mi][ni][e] *= alpha[mi][e >> 1];
        __syncthreads();   // P tile + sreds complete

        // ---- l update ----
#pragma unroll
        for (int mi = 0; mi < 2; mi++) {
#pragma unroll
            for (int rr = 0; rr < 2; rr++) {
                const int row = wm + mi * 16 + rr * 8 + g;
                float ts = (sm.sreds[0][row] + sm.sreds[1][row]) +
                           (sm.sreds[2][row] + sm.sreds[3][row]);
                l_st[mi][rr] = l_st[mi][rr] * alpha[mi][rr] + ts;
            }
        }

        // ---- O += P.V ; this warp: rows [wm,wm+32), d [wc*16,+16) ----
#pragma unroll
        for (int ks = 0; ks < 16; ks++) {
            const int kb = ks * 8;
            uint32_t a[2][4];
#pragma unroll
            for (int mi = 0; mi < 2; mi++) {
                int r = wm + mi * 16;
                a[mi][0] = Pb[(r + g) * SP_ + kb + tg];
                a[mi][1] = Pb[(r + g + 8) * SP_ + kb + tg];
                a[mi][2] = Pb[(r + g) * SP_ + kb + tg + 4];
                a[mi][3] = Pb[(r + g + 8) * SP_ + kb + tg + 4];
            }
#pragma unroll
            for (int ni = 0; ni < 2; ni++) {
                const int n = wc * 16 + ni * 8 + g;
                uint32_t b[2] = { sm.Vs[kb + tg][n], sm.Vs[kb + tg + 4][n] };
                mma8(acc_o[0][ni], a[0], b);
                mma8(acc_o[1][ni], a[1], b);
            }
        }
    }

    // ---- epilogue: O /= l, scatter to g_attn[b, s, h*64 + d] ----
#pragma unroll
    for (int mi = 0; mi < 2; mi++) {
#pragma unroll
        for (int rr = 0; rr < 2; rr++) {
            const int row = wm + mi * 16 + rr * 8 + g;
            const float inv = 1.0f / l_st[mi][rr];
#pragma unroll
            for (int ni = 0; ni < 2; ni++) {
                const int d = wc * 16 + ni * 8 + 2 * tg;
                float2 o;
                o.x = acc_o[mi][ni][rr * 2 + 0] * inv;
                o.y = acc_o[mi][ni][rr * 2 + 1] * inv;
                *(float2*)&g_attn[(size_t)(bb * S_ + i0 + row) * D_ + h * 64 + d] = o;
            }
        }
    }
}

// ------------------------------------------------------------------------
extern "C" void kernel_launch(void* const* d_in, const int* in_sizes, int n_in,
                              void* d_out, int out_size)
{
    const float* q    = (const float*)d_in[0];
    const float* k    = (const float*)d_in[1];
    const float* v    = (const float*)d_in[2];
    const int*   mask = (const int*)  d_in[3];
    const float* Wq   = (const float*)d_in[4];
    const float* bq   = (const float*)d_in[5];
    const float* Wk   = (const float*)d_in[6];
    const float* bk   = (const float*)d_in[7];
    const float* Wv   = (const float*)d_in[8];
    const float* bv   = (const float*)d_in[9];
    const float* Wo   = (const float*)d_in[10];
    const float* bo   = (const float*)d_in[11];
    float* out = (float*)d_out;

    // opt-in to >48KB dynamic smem (host-side attribute set, idempotent)
    cudaFuncSetAttribute(proj_tf32<0>, cudaFuncAttributeMaxDynamicSharedMemorySize, (int)sizeof(ProjSmem));
    cudaFuncSetAttribute(proj_tf32<1>, cudaFuncAttributeMaxDynamicSharedMemorySize, (int)sizeof(ProjSmem));
    cudaFuncSetAttribute(proj_tf32<2>, cudaFuncAttributeMaxDynamicSharedMemorySize, (int)sizeof(ProjSmem));
    cudaFuncSetAttribute(proj_tf32<3>, cudaFuncAttributeMaxDynamicSharedMemorySize, (int)sizeof(ProjSmem));
    cudaFuncSetAttribute(flash_tf32,   cudaFuncAttributeMaxDynamicSharedMemorySize, (int)sizeof(FlashSmem));

    dim3 gproj(D_ / 128, M_ / 128);          // (8, 32)
    proj_tf32<0><<<gproj, 512, sizeof(ProjSmem)>>>(q, Wq, bq, nullptr);
    proj_tf32<1><<<gproj, 512, sizeof(ProjSmem)>>>(k, Wk, bk, nullptr);
    proj_tf32<2><<<gproj, 512, sizeof(ProjSmem)>>>(v, Wv, bv, nullptr);

    dim3 gfl(S_ / 64, BH_);                  // (32, 32) = 1024 blocks
    flash_tf32<<<gfl, 256, sizeof(FlashSmem)>>>(mask);

    proj_tf32<3><<<gproj, 512, sizeof(ProjSmem)>>>(nullptr, Wo, bo, out);
}